// round 12
// baseline (speedup 1.0000x reference)
#include <cuda_runtime.h>
#include <math.h>

#define SQ 2048
#define DM 768
#define NH 12
#define DK 64
#define BB 2
#define MTOT (BB*SQ)          // 4096
#define ASCALE 0.125f         // 1/sqrt(64)

// Scratch (allocation-free rule: __device__ globals)
__device__ float g_q [MTOT*DM];
__device__ float g_k [MTOT*DM];
__device__ float g_v [MTOT*DM];
__device__ float g_mh[MTOT*DM];
__device__ float g_t1[MTOT*DM];

// ---------------------------------------------------------------------------
// C[M,N] = A[M,K] @ B[N,K]^T + bias   (torch Linear: y = x W^T + b)
// Tile 128(m) x 64(n), BK=16, 256 threads, 8x4 per-thread fragment.
// ---------------------------------------------------------------------------
__global__ void __launch_bounds__(256) gemm_nt_bias(
    const float* __restrict__ A, const float* __restrict__ Bw,
    const float* __restrict__ bias, float* __restrict__ C,
    int K, int N)
{
    __shared__ float As[16*128];   // [k][m]
    __shared__ float Bs[16*64];    // [k][n]
    const int tid = threadIdx.x;
    const int m0  = blockIdx.x * 128;
    const int n0  = blockIdx.y * 64;
    const int tm  = tid >> 4;      // 0..15
    const int tn  = tid & 15;      // 0..15

    float acc[2][4][4];
    #pragma unroll
    for (int hh = 0; hh < 2; hh++)
        #pragma unroll
        for (int i = 0; i < 4; i++)
            #pragma unroll
            for (int j = 0; j < 4; j++) acc[hh][i][j] = 0.f;

    for (int k0 = 0; k0 < K; k0 += 16) {
        // A tile 128x16 -> As[k][m] (transposed)
        #pragma unroll
        for (int l = 0; l < 2; l++) {
            int idx = tid + l*256;
            int row = idx >> 2;
            int c4  = (idx & 3) * 4;
            const float4 v = *(const float4*)(A + (size_t)(m0+row)*K + k0 + c4);
            As[(c4+0)*128 + row] = v.x;
            As[(c4+1)*128 + row] = v.y;
            As[(c4+2)*128 + row] = v.z;
            As[(c4+3)*128 + row] = v.w;
        }
        // B tile 64x16 -> Bs[k][n] (transposed)
        {
            int row = tid >> 2;
            int c4  = (tid & 3) * 4;
            const float4 v = *(const float4*)(Bw + (size_t)(n0+row)*K + k0 + c4);
            Bs[(c4+0)*64 + row] = v.x;
            Bs[(c4+1)*64 + row] = v.y;
            Bs[(c4+2)*64 + row] = v.z;
            Bs[(c4+3)*64 + row] = v.w;
        }
        __syncthreads();
        #pragma unroll
        for (int k = 0; k < 16; k++) {
            float4 a0 = *(float4*)&As[k*128 + tm*4];
            float4 a1 = *(float4*)&As[k*128 + 64 + tm*4];
            float4 b0 = *(float4*)&Bs[k*64 + tn*4];
            float am[2][4] = {{a0.x,a0.y,a0.z,a0.w},{a1.x,a1.y,a1.z,a1.w}};
            float bn[4]    = {b0.x,b0.y,b0.z,b0.w};
            #pragma unroll
            for (int hh = 0; hh < 2; hh++)
                #pragma unroll
                for (int i = 0; i < 4; i++)
                    #pragma unroll
                    for (int j = 0; j < 4; j++)
                        acc[hh][i][j] = fmaf(am[hh][i], bn[j], acc[hh][i][j]);
        }
        __syncthreads();
    }

    const float4 bv = *(const float4*)(bias + n0 + tn*4);
    #pragma unroll
    for (int hh = 0; hh < 2; hh++) {
        #pragma unroll
        for (int i = 0; i < 4; i++) {
            int m = m0 + hh*64 + tm*4 + i;
            float4 o;
            o.x = acc[hh][i][0] + bv.x;
            o.y = acc[hh][i][1] + bv.y;
            o.z = acc[hh][i][2] + bv.z;
            o.w = acc[hh][i][3] + bv.w;
            *(float4*)(C + (size_t)m*N + n0 + tn*4) = o;
        }
    }
}

// ---------------------------------------------------------------------------
// Fused attention per (b,h): for a 128-row Q tile,
//   acc[i,d] = sum_t (q[i,:]·k[t,:]) * v[t,d]       (streamed over 64-wide t-blocks)
// epilogue: logits = acc*ASCALE, softmax over d (dk=64), write to flat mh buffer.
// The quirky reshape makes Q/K/V per (b,h) contiguous [2048,64] matrices.
// ---------------------------------------------------------------------------
__global__ void __launch_bounds__(256) attn_fused(
    const float* __restrict__ gq, const float* __restrict__ gk,
    const float* __restrict__ gv, float* __restrict__ gmh)
{
    extern __shared__ float sm[];
    float* Qs = sm;                 // [d][i]   64 x 128
    float* Ks = Qs + 64*128;        // [d][j]   64 x 64
    float* Vs = Ks + 64*64;         // [j][d]   64 x 64
    float* Ss = Vs + 64*64;         // [i][j]   128 x 65 (pad)

    const int tid = threadIdx.x;
    const int bh  = blockIdx.y;
    const int b   = bh / NH;
    const int h   = bh - b*NH;
    const size_t base = (size_t)b*SQ*DM + (size_t)h*SQ*DK;
    const float* Q  = gq + base;
    const float* Kp = gk + base;
    const float* Vp = gv + base;
    float*       Out = gmh + base;
    const int i0 = blockIdx.x * 128;

    const int tx = tid & 7;         // d/j group (8 groups x 8)
    const int ty = tid >> 3;        // i group   (32 groups x 4)

    // Load Q tile [128 x 64] transposed into Qs[d][i]  (once per CTA)
    #pragma unroll
    for (int l = 0; l < 8; l++) {
        int idx = tid + l*256;
        int i   = idx >> 4;
        int d4  = (idx & 15) * 4;
        const float4 v = *(const float4*)(Q + (size_t)(i0+i)*DK + d4);
        Qs[(d4+0)*128 + i] = v.x;
        Qs[(d4+1)*128 + i] = v.y;
        Qs[(d4+2)*128 + i] = v.z;
        Qs[(d4+3)*128 + i] = v.w;
    }

    float acc[4][8];
    #pragma unroll
    for (int i = 0; i < 4; i++)
        #pragma unroll
        for (int d = 0; d < 8; d++) acc[i][d] = 0.f;

    for (int j0 = 0; j0 < SQ; j0 += 64) {
        __syncthreads();   // prev phase2 done reading Vs/Ss; 1st iter: no-op
        // Load K block -> Ks[d][j] (transposed), V block -> Vs[j][d]
        #pragma unroll
        for (int l = 0; l < 4; l++) {
            int idx = tid + l*256;
            int j   = idx >> 4;
            int d4  = (idx & 15) * 4;
            const float4 kv = *(const float4*)(Kp + (size_t)(j0+j)*DK + d4);
            Ks[(d4+0)*64 + j] = kv.x;
            Ks[(d4+1)*64 + j] = kv.y;
            Ks[(d4+2)*64 + j] = kv.z;
            Ks[(d4+3)*64 + j] = kv.w;
            const float4 vv = *(const float4*)(Vp + (size_t)(j0+j)*DK + d4);
            *(float4*)&Vs[j*64 + d4] = vv;
        }
        __syncthreads();

        // Phase 1: S[i,j] = sum_d Q[i,d] K[j,d]
        float s[4][8];
        #pragma unroll
        for (int i = 0; i < 4; i++)
            #pragma unroll
            for (int j = 0; j < 8; j++) s[i][j] = 0.f;
        #pragma unroll 8
        for (int d = 0; d < 64; d++) {
            float4 q4 = *(float4*)&Qs[d*128 + ty*4];
            float4 ka = *(float4*)&Ks[d*64 + tx*8];
            float4 kb = *(float4*)&Ks[d*64 + tx*8 + 4];
            float qa[4] = {q4.x,q4.y,q4.z,q4.w};
            float kk[8] = {ka.x,ka.y,ka.z,ka.w,kb.x,kb.y,kb.z,kb.w};
            #pragma unroll
            for (int i = 0; i < 4; i++)
                #pragma unroll
                for (int j = 0; j < 8; j++)
                    s[i][j] = fmaf(qa[i], kk[j], s[i][j]);
        }
        #pragma unroll
        for (int i = 0; i < 4; i++)
            #pragma unroll
            for (int j = 0; j < 8; j++)
                Ss[(ty*4+i)*65 + tx*8 + j] = s[i][j];
        __syncthreads();

        // Phase 2: acc[i,d] += S[i,j] * V[j,d]
        #pragma unroll 8
        for (int j = 0; j < 64; j++) {
            float s0 = Ss[(ty*4+0)*65 + j];
            float s1 = Ss[(ty*4+1)*65 + j];
            float s2 = Ss[(ty*4+2)*65 + j];
            float s3 = Ss[(ty*4+3)*65 + j];
            float4 va = *(float4*)&Vs[j*64 + tx*8];
            float4 vb = *(float4*)&Vs[j*64 + tx*8 + 4];
            float vv[8] = {va.x,va.y,va.z,va.w,vb.x,vb.y,vb.z,vb.w};
            float ssr[4] = {s0,s1,s2,s3};
            #pragma unroll
            for (int i = 0; i < 4; i++)
                #pragma unroll
                for (int d = 0; d < 8; d++)
                    acc[i][d] = fmaf(ssr[i], vv[d], acc[i][d]);
        }
    }

    // Epilogue: scale + softmax over d (64 values across 8 tx lanes, same warp)
    #pragma unroll
    for (int i = 0; i < 4; i++) {
        float v[8];
        float mx = -3.4e38f;
        #pragma unroll
        for (int d = 0; d < 8; d++) { v[d] = acc[i][d] * ASCALE; mx = fmaxf(mx, v[d]); }
        #pragma unroll
        for (int o = 1; o < 8; o <<= 1) mx = fmaxf(mx, __shfl_xor_sync(0xffffffffu, mx, o));
        float sum = 0.f;
        #pragma unroll
        for (int d = 0; d < 8; d++) { v[d] = expf(v[d] - mx); sum += v[d]; }
        #pragma unroll
        for (int o = 1; o < 8; o <<= 1) sum += __shfl_xor_sync(0xffffffffu, sum, o);
        float inv = 1.f / sum;
        size_t off = (size_t)(i0 + ty*4 + i)*DK + tx*8;
        float4 o0 = make_float4(v[0]*inv, v[1]*inv, v[2]*inv, v[3]*inv);
        float4 o1 = make_float4(v[4]*inv, v[5]*inv, v[6]*inv, v[7]*inv);
        *(float4*)(Out + off)     = o0;
        *(float4*)(Out + off + 4) = o1;
    }
}

// ---------------------------------------------------------------------------
extern "C" void kernel_launch(void* const* d_in, const int* in_sizes, int n_in,
                              void* d_out, int out_size)
{
    const float* x  = (const float*)d_in[0];
    const float* Wq = (const float*)d_in[1];
    const float* bq = (const float*)d_in[2];
    const float* Wk = (const float*)d_in[3];
    const float* bk = (const float*)d_in[4];
    const float* Wv = (const float*)d_in[5];
    const float* bv = (const float*)d_in[6];
    const float* Wo = (const float*)d_in[7];
    const float* bo = (const float*)d_in[8];
    const float* Wf = (const float*)d_in[9];
    const float* bf = (const float*)d_in[10];

    float *q, *k, *v, *mh, *t1;
    cudaGetSymbolAddress((void**)&q,  g_q);
    cudaGetSymbolAddress((void**)&k,  g_k);
    cudaGetSymbolAddress((void**)&v,  g_v);
    cudaGetSymbolAddress((void**)&mh, g_mh);
    cudaGetSymbolAddress((void**)&t1, g_t1);

    const int SMEM_ATTN = (64*128 + 64*64 + 64*64 + 128*65) * (int)sizeof(float); // 98816 B
    cudaFuncSetAttribute(attn_fused, cudaFuncAttributeMaxDynamicSharedMemorySize, SMEM_ATTN);

    dim3 gg(MTOT/128, DM/64);   // 32 x 12

    gemm_nt_bias<<<gg, 256>>>(x, Wq, bq, q, DM, DM);
    gemm_nt_bias<<<gg, 256>>>(x, Wk, bk, k, DM, DM);
    gemm_nt_bias<<<gg, 256>>>(x, Wv, bv, v, DM, DM);

    attn_fused<<<dim3(SQ/128, BB*NH), 256, SMEM_ATTN>>>(q, k, v, mh);

    gemm_nt_bias<<<gg, 256>>>(mh, Wo, bo, t1, DM, DM);
    gemm_nt_bias<<<gg, 256>>>(t1, Wf, bf, (float*)d_out, DM, DM);
}

// round 13
// speedup vs baseline: 1.0023x; 1.0023x over previous
#include <cuda_runtime.h>
#include <math.h>

#define SQ 2048
#define DM 768
#define NH 12
#define DK 64
#define BB 2
#define MTOT (BB*SQ)          // 4096
#define ASCALE 0.125f         // 1/sqrt(64)

// Scratch (allocation-free rule: __device__ globals)
__device__ float g_q [MTOT*DM];
__device__ float g_k [MTOT*DM];
__device__ float g_v [MTOT*DM];
__device__ float g_mh[MTOT*DM];
__device__ float g_t1[MTOT*DM];

// ---------------------------------------------------------------------------
// C[M,N] = A[M,K] @ B[N,K]^T + bias   (torch Linear: y = x W^T + b)
// Tile 128(m) x 64(n), BK=16, 256 threads, 8x4 per-thread fragment.
// ---------------------------------------------------------------------------
__global__ void __launch_bounds__(256) gemm_nt_bias(
    const float* __restrict__ A, const float* __restrict__ Bw,
    const float* __restrict__ bias, float* __restrict__ C,
    int K, int N)
{
    __shared__ float As[16*128];   // [k][m]
    __shared__ float Bs[16*64];    // [k][n]
    const int tid = threadIdx.x;
    const int m0  = blockIdx.x * 128;
    const int n0  = blockIdx.y * 64;
    const int tm  = tid >> 4;      // 0..15
    const int tn  = tid & 15;      // 0..15

    float acc[2][4][4];
    #pragma unroll
    for (int hh = 0; hh < 2; hh++)
        #pragma unroll
        for (int i = 0; i < 4; i++)
            #pragma unroll
            for (int j = 0; j < 4; j++) acc[hh][i][j] = 0.f;

    for (int k0 = 0; k0 < K; k0 += 16) {
        // A tile 128x16 -> As[k][m] (transposed)
        #pragma unroll
        for (int l = 0; l < 2; l++) {
            int idx = tid + l*256;
            int row = idx >> 2;
            int c4  = (idx & 3) * 4;
            const float4 v = *(const float4*)(A + (size_t)(m0+row)*K + k0 + c4);
            As[(c4+0)*128 + row] = v.x;
            As[(c4+1)*128 + row] = v.y;
            As[(c4+2)*128 + row] = v.z;
            As[(c4+3)*128 + row] = v.w;
        }
        // B tile 64x16 -> Bs[k][n] (transposed)
        {
            int row = tid >> 2;
            int c4  = (tid & 3) * 4;
            const float4 v = *(const float4*)(Bw + (size_t)(n0+row)*K + k0 + c4);
            Bs[(c4+0)*64 + row] = v.x;
            Bs[(c4+1)*64 + row] = v.y;
            Bs[(c4+2)*64 + row] = v.z;
            Bs[(c4+3)*64 + row] = v.w;
        }
        __syncthreads();
        #pragma unroll
        for (int k = 0; k < 16; k++) {
            float4 a0 = *(float4*)&As[k*128 + tm*4];
            float4 a1 = *(float4*)&As[k*128 + 64 + tm*4];
            float4 b0 = *(float4*)&Bs[k*64 + tn*4];
            float am[2][4] = {{a0.x,a0.y,a0.z,a0.w},{a1.x,a1.y,a1.z,a1.w}};
            float bn[4]    = {b0.x,b0.y,b0.z,b0.w};
            #pragma unroll
            for (int hh = 0; hh < 2; hh++)
                #pragma unroll
                for (int i = 0; i < 4; i++)
                    #pragma unroll
                    for (int j = 0; j < 4; j++)
                        acc[hh][i][j] = fmaf(am[hh][i], bn[j], acc[hh][i][j]);
        }
        __syncthreads();
    }

    const float4 bv = *(const float4*)(bias + n0 + tn*4);
    #pragma unroll
    for (int hh = 0; hh < 2; hh++) {
        #pragma unroll
        for (int i = 0; i < 4; i++) {
            int m = m0 + hh*64 + tm*4 + i;
            float4 o;
            o.x = acc[hh][i][0] + bv.x;
            o.y = acc[hh][i][1] + bv.y;
            o.z = acc[hh][i][2] + bv.z;
            o.w = acc[hh][i][3] + bv.w;
            *(float4*)(C + (size_t)m*N + n0 + tn*4) = o;
        }
    }
}

// ---------------------------------------------------------------------------
// Fused attention per (b,h): for a 128-row Q tile,
//   acc[i,d] = sum_t (q[i,:]·k[t,:]) * v[t,d]       (streamed over 64-wide t-blocks)
// epilogue: logits = acc*ASCALE, softmax over d (dk=64), write to flat mh buffer.
// The quirky reshape makes Q/K/V per (b,h) contiguous [2048,64] matrices.
// ---------------------------------------------------------------------------
__global__ void __launch_bounds__(256) attn_fused(
    const float* __restrict__ gq, const float* __restrict__ gk,
    const float* __restrict__ gv, float* __restrict__ gmh)
{
    extern __shared__ float sm[];
    float* Qs = sm;                 // [d][i]   64 x 128
    float* Ks = Qs + 64*128;        // [d][j]   64 x 64
    float* Vs = Ks + 64*64;         // [j][d]   64 x 64
    float* Ss = Vs + 64*64;         // [i][j]   128 x 65 (pad)

    const int tid = threadIdx.x;
    const int bh  = blockIdx.y;
    const int b   = bh / NH;
    const int h   = bh - b*NH;
    const size_t base = (size_t)b*SQ*DM + (size_t)h*SQ*DK;
    const float* Q  = gq + base;
    const float* Kp = gk + base;
    const float* Vp = gv + base;
    float*       Out = gmh + base;
    const int i0 = blockIdx.x * 128;

    const int tx = tid & 7;         // d/j group (8 groups x 8)
    const int ty = tid >> 3;        // i group   (32 groups x 4)

    // Load Q tile [128 x 64] transposed into Qs[d][i]  (once per CTA)
    #pragma unroll
    for (int l = 0; l < 8; l++) {
        int idx = tid + l*256;
        int i   = idx >> 4;
        int d4  = (idx & 15) * 4;
        const float4 v = *(const float4*)(Q + (size_t)(i0+i)*DK + d4);
        Qs[(d4+0)*128 + i] = v.x;
        Qs[(d4+1)*128 + i] = v.y;
        Qs[(d4+2)*128 + i] = v.z;
        Qs[(d4+3)*128 + i] = v.w;
    }

    float acc[4][8];
    #pragma unroll
    for (int i = 0; i < 4; i++)
        #pragma unroll
        for (int d = 0; d < 8; d++) acc[i][d] = 0.f;

    for (int j0 = 0; j0 < SQ; j0 += 64) {
        __syncthreads();   // prev phase2 done reading Vs/Ss; 1st iter: no-op
        // Load K block -> Ks[d][j] (transposed), V block -> Vs[j][d]
        #pragma unroll
        for (int l = 0; l < 4; l++) {
            int idx = tid + l*256;
            int j   = idx >> 4;
            int d4  = (idx & 15) * 4;
            const float4 kv = *(const float4*)(Kp + (size_t)(j0+j)*DK + d4);
            Ks[(d4+0)*64 + j] = kv.x;
            Ks[(d4+1)*64 + j] = kv.y;
            Ks[(d4+2)*64 + j] = kv.z;
            Ks[(d4+3)*64 + j] = kv.w;
            const float4 vv = *(const float4*)(Vp + (size_t)(j0+j)*DK + d4);
            *(float4*)&Vs[j*64 + d4] = vv;
        }
        __syncthreads();

        // Phase 1: S[i,j] = sum_d Q[i,d] K[j,d]
        float s[4][8];
        #pragma unroll
        for (int i = 0; i < 4; i++)
            #pragma unroll
            for (int j = 0; j < 8; j++) s[i][j] = 0.f;
        #pragma unroll 8
        for (int d = 0; d < 64; d++) {
            float4 q4 = *(float4*)&Qs[d*128 + ty*4];
            float4 ka = *(float4*)&Ks[d*64 + tx*8];
            float4 kb = *(float4*)&Ks[d*64 + tx*8 + 4];
            float qa[4] = {q4.x,q4.y,q4.z,q4.w};
            float kk[8] = {ka.x,ka.y,ka.z,ka.w,kb.x,kb.y,kb.z,kb.w};
            #pragma unroll
            for (int i = 0; i < 4; i++)
                #pragma unroll
                for (int j = 0; j < 8; j++)
                    s[i][j] = fmaf(qa[i], kk[j], s[i][j]);
        }
        #pragma unroll
        for (int i = 0; i < 4; i++)
            #pragma unroll
            for (int j = 0; j < 8; j++)
                Ss[(ty*4+i)*65 + tx*8 + j] = s[i][j];
        __syncthreads();

        // Phase 2: acc[i,d] += S[i,j] * V[j,d]
        #pragma unroll 8
        for (int j = 0; j < 64; j++) {
            float s0 = Ss[(ty*4+0)*65 + j];
            float s1 = Ss[(ty*4+1)*65 + j];
            float s2 = Ss[(ty*4+2)*65 + j];
            float s3 = Ss[(ty*4+3)*65 + j];
            float4 va = *(float4*)&Vs[j*64 + tx*8];
            float4 vb = *(float4*)&Vs[j*64 + tx*8 + 4];
            float vv[8] = {va.x,va.y,va.z,va.w,vb.x,vb.y,vb.z,vb.w};
            float ssr[4] = {s0,s1,s2,s3};
            #pragma unroll
            for (int i = 0; i < 4; i++)
                #pragma unroll
                for (int d = 0; d < 8; d++)
                    acc[i][d] = fmaf(ssr[i], vv[d], acc[i][d]);
        }
    }

    // Epilogue: scale + softmax over d (64 values across 8 tx lanes, same warp)
    #pragma unroll
    for (int i = 0; i < 4; i++) {
        float v[8];
        float mx = -3.4e38f;
        #pragma unroll
        for (int d = 0; d < 8; d++) { v[d] = acc[i][d] * ASCALE; mx = fmaxf(mx, v[d]); }
        #pragma unroll
        for (int o = 1; o < 8; o <<= 1) mx = fmaxf(mx, __shfl_xor_sync(0xffffffffu, mx, o));
        float sum = 0.f;
        #pragma unroll
        for (int d = 0; d < 8; d++) { v[d] = expf(v[d] - mx); sum += v[d]; }
        #pragma unroll
        for (int o = 1; o < 8; o <<= 1) sum += __shfl_xor_sync(0xffffffffu, sum, o);
        float inv = 1.f / sum;
        size_t off = (size_t)(i0 + ty*4 + i)*DK + tx*8;
        float4 o0 = make_float4(v[0]*inv, v[1]*inv, v[2]*inv, v[3]*inv);
        float4 o1 = make_float4(v[4]*inv, v[5]*inv, v[6]*inv, v[7]*inv);
        *(float4*)(Out + off)     = o0;
        *(float4*)(Out + off + 4) = o1;
    }
}

// ---------------------------------------------------------------------------
extern "C" void kernel_launch(void* const* d_in, const int* in_sizes, int n_in,
                              void* d_out, int out_size)
{
    const float* x  = (const float*)d_in[0];
    const float* Wq = (const float*)d_in[1];
    const float* bq = (const float*)d_in[2];
    const float* Wk = (const float*)d_in[3];
    const float* bk = (const float*)d_in[4];
    const float* Wv = (const float*)d_in[5];
    const float* bv = (const float*)d_in[6];
    const float* Wo = (const float*)d_in[7];
    const float* bo = (const float*)d_in[8];
    const float* Wf = (const float*)d_in[9];
    const float* bf = (const float*)d_in[10];

    float *q, *k, *v, *mh, *t1;
    cudaGetSymbolAddress((void**)&q,  g_q);
    cudaGetSymbolAddress((void**)&k,  g_k);
    cudaGetSymbolAddress((void**)&v,  g_v);
    cudaGetSymbolAddress((void**)&mh, g_mh);
    cudaGetSymbolAddress((void**)&t1, g_t1);

    const int SMEM_ATTN = (64*128 + 64*64 + 64*64 + 128*65) * (int)sizeof(float); // 98816 B
    cudaFuncSetAttribute(attn_fused, cudaFuncAttributeMaxDynamicSharedMemorySize, SMEM_ATTN);

    dim3 gg(MTOT/128, DM/64);   // 32 x 12

    gemm_nt_bias<<<gg, 256>>>(x, Wq, bq, q, DM, DM);
    gemm_nt_bias<<<gg, 256>>>(x, Wk, bk, k, DM, DM);
    gemm_nt_bias<<<gg, 256>>>(x, Wv, bv, v, DM, DM);

    attn_fused<<<dim3(SQ/128, BB*NH), 256, SMEM_ATTN>>>(q, k, v, mh);

    gemm_nt_bias<<<gg, 256>>>(mh, Wo, bo, t1, DM, DM);
    gemm_nt_bias<<<gg, 256>>>(t1, Wf, bf, (float*)d_out, DM, DM);
}